// round 16
// baseline (speedup 1.0000x reference)
#include <cuda_runtime.h>

// SparseAudioModel gather — R16 = R15 resubmitted (round 15 was an infra
// failure: "GB300 container failed twice"; the .nc experiment never ran).
// R12 (best: 10.72us) with the one untested qualifier: ld.global.nc
// (read-only L1tex routing) instead of ld.global.cs on the input loads.
// R7's .nc attempt was invalid (32-reg clamp serialized the batch); this run
// keeps the proven 80-reg held batch. If neutral/worse, R12 is final.
//
//   out[b, s] = sum_e x[b, e, s - time_e],  time_e = idx[b,e]*256, active iff time_e <= s
//
// Proven ingredients: scatter->gather inversion (no atomics), LDG.128 512B
// warp requests with a held 16-load batch, mirror-pair uniform tiles,
// 1024 x 64-thread co-resident blocks, .cs streaming stores.

#define N_SAMPLES 32768
#define N_EVENTS  64
#define STEP_SIZE 256
#define BATCH     16
#define TILE      256                 // one tile = 64 threads * float4
#define NTILES    (N_SAMPLES / TILE)  // 128
#define GRP       8

__global__ __launch_bounds__(64, 12) void sparse_audio_gather(
    const float* __restrict__ x,      // [B, E, S]
    const int*   __restrict__ idx,    // [B, E]
    float*       __restrict__ out)    // [B, S]
{
    __shared__ int s_time[N_EVENTS];

    const int k = blockIdx.x;         // tile pair id 0..63
    const int b = blockIdx.y;
    const int t = threadIdx.x;

    s_time[t] = idx[b * N_EVENTS + t] * STEP_SIZE;   // 64 threads, 64 events
    __syncthreads();

    const int s_lo = k * TILE + t * 4;                 // light tile
    const int s_hi = (NTILES - 1 - k) * TILE + t * 4;  // heavy tile

    const float* xb = x + (size_t)b * N_EVENTS * N_SAMPLES;

    float4 al = make_float4(0.f, 0.f, 0.f, 0.f);
    float4 ah = make_float4(0.f, 0.f, 0.f, 0.f);

    #pragma unroll
    for (int g = 0; g < N_EVENTS; g += GRP) {
        float4 vl[GRP], vh[GRP];

        // ---- issue 16 predicated read-only LDG.128, no consumption yet ----
        #pragma unroll
        for (int j = 0; j < GRP; ++j) {
            const int e    = g + j;
            const int time = s_time[e];
            const float* pe = xb + (size_t)e * N_SAMPLES - time;

            vl[j] = make_float4(0.f, 0.f, 0.f, 0.f);
            vh[j] = make_float4(0.f, 0.f, 0.f, 0.f);

            asm("{\n\t"
                ".reg .pred p;\n\t"
                "setp.le.s32 p, %4, %5;\n\t"
                "@p ld.global.nc.v4.f32 {%0, %1, %2, %3}, [%6];\n\t"
                "}"
                : "+f"(vl[j].x), "+f"(vl[j].y), "+f"(vl[j].z), "+f"(vl[j].w)
                : "r"(time), "r"(s_lo), "l"(pe + s_lo));

            asm("{\n\t"
                ".reg .pred p;\n\t"
                "setp.le.s32 p, %4, %5;\n\t"
                "@p ld.global.nc.v4.f32 {%0, %1, %2, %3}, [%6];\n\t"
                "}"
                : "+f"(vh[j].x), "+f"(vh[j].y), "+f"(vh[j].z), "+f"(vh[j].w)
                : "r"(time), "r"(s_hi), "l"(pe + s_hi));
        }

        // ---- consume ----
        #pragma unroll
        for (int j = 0; j < GRP; ++j) {
            al.x += vl[j].x; al.y += vl[j].y; al.z += vl[j].z; al.w += vl[j].w;
            ah.x += vh[j].x; ah.y += vh[j].y; ah.z += vh[j].z; ah.w += vh[j].w;
        }
    }

    float* ob = out + (size_t)b * N_SAMPLES;
    asm("st.global.cs.v4.f32 [%0], {%1, %2, %3, %4};"
        :: "l"(ob + s_lo), "f"(al.x), "f"(al.y), "f"(al.z), "f"(al.w) : "memory");
    asm("st.global.cs.v4.f32 [%0], {%1, %2, %3, %4};"
        :: "l"(ob + s_hi), "f"(ah.x), "f"(ah.y), "f"(ah.z), "f"(ah.w) : "memory");
}

extern "C" void kernel_launch(void* const* d_in, const int* in_sizes, int n_in,
                              void* d_out, int out_size)
{
    const float* x   = (const float*)d_in[0];   // [16, 64, 32768] float32
    const int*   idx = (const int*)  d_in[1];   // [16, 64] int32
    float*       out = (float*)d_out;           // [16, 1, 32768] float32

    dim3 block(64);
    dim3 grid(NTILES / 2, BATCH);               // (64, 16) = 1024 blocks
    sparse_audio_gather<<<grid, block>>>(x, idx, out);
}

// round 17
// speedup vs baseline: 1.2716x; 1.2716x over previous
#include <cuda_runtime.h>

// SparseAudioModel gather — FINAL (R12 config; best verified 10.72us,
// reproduced 10.75us; ~6.5 TB/s steady-state ≈ 94% of achievable HBM ceiling
// at algorithmic-minimum traffic).
//
//   out[b, s] = sum_e x[b, e, s - time_e],  time_e = idx[b,e]*256, active iff time_e <= s
//
// Validated levers (12.8 -> 10.72):
//  - LDG.128 predicated loads (512B warp requests) with a genuinely-held
//    16-load register batch (__launch_bounds__(64,12) -> 80 regs)  [R10, -15%]
//  - fine-grained uniform mirror-pair blocks: 1024 x 64 threads = 6.92/SM,
//    +1.2% wave quantization                                        [R12, -2%]
// Falsified: deeper MLP (R9/R13), occupancy (R2), smem indirection (R3),
// issue order (R4), TMA bulk (R6), cp.async (R8), >2KB contiguity (R11),
// .nc read-only path (R16: -27%), L2 fetch hints (R7).

#define N_SAMPLES 32768
#define N_EVENTS  64
#define STEP_SIZE 256
#define BATCH     16
#define TILE      256                 // one tile = 64 threads * float4
#define NTILES    (N_SAMPLES / TILE)  // 128
#define GRP       8

__global__ __launch_bounds__(64, 12) void sparse_audio_gather(
    const float* __restrict__ x,      // [B, E, S]
    const int*   __restrict__ idx,    // [B, E]
    float*       __restrict__ out)    // [B, S]
{
    __shared__ int s_time[N_EVENTS];

    const int k = blockIdx.x;         // tile pair id 0..63
    const int b = blockIdx.y;
    const int t = threadIdx.x;

    s_time[t] = idx[b * N_EVENTS + t] * STEP_SIZE;   // 64 threads, 64 events
    __syncthreads();

    const int s_lo = k * TILE + t * 4;                 // light tile
    const int s_hi = (NTILES - 1 - k) * TILE + t * 4;  // heavy tile

    const float* xb = x + (size_t)b * N_EVENTS * N_SAMPLES;

    float4 al = make_float4(0.f, 0.f, 0.f, 0.f);
    float4 ah = make_float4(0.f, 0.f, 0.f, 0.f);

    #pragma unroll
    for (int g = 0; g < N_EVENTS; g += GRP) {
        float4 vl[GRP], vh[GRP];

        // ---- issue 16 predicated LDG.128, no consumption yet ----
        #pragma unroll
        for (int j = 0; j < GRP; ++j) {
            const int e    = g + j;
            const int time = s_time[e];
            const float* pe = xb + (size_t)e * N_SAMPLES - time;

            vl[j] = make_float4(0.f, 0.f, 0.f, 0.f);
            vh[j] = make_float4(0.f, 0.f, 0.f, 0.f);

            asm("{\n\t"
                ".reg .pred p;\n\t"
                "setp.le.s32 p, %4, %5;\n\t"
                "@p ld.global.cs.v4.f32 {%0, %1, %2, %3}, [%6];\n\t"
                "}"
                : "+f"(vl[j].x), "+f"(vl[j].y), "+f"(vl[j].z), "+f"(vl[j].w)
                : "r"(time), "r"(s_lo), "l"(pe + s_lo));

            asm("{\n\t"
                ".reg .pred p;\n\t"
                "setp.le.s32 p, %4, %5;\n\t"
                "@p ld.global.cs.v4.f32 {%0, %1, %2, %3}, [%6];\n\t"
                "}"
                : "+f"(vh[j].x), "+f"(vh[j].y), "+f"(vh[j].z), "+f"(vh[j].w)
                : "r"(time), "r"(s_hi), "l"(pe + s_hi));
        }

        // ---- consume ----
        #pragma unroll
        for (int j = 0; j < GRP; ++j) {
            al.x += vl[j].x; al.y += vl[j].y; al.z += vl[j].z; al.w += vl[j].w;
            ah.x += vh[j].x; ah.y += vh[j].y; ah.z += vh[j].z; ah.w += vh[j].w;
        }
    }

    float* ob = out + (size_t)b * N_SAMPLES;
    asm("st.global.cs.v4.f32 [%0], {%1, %2, %3, %4};"
        :: "l"(ob + s_lo), "f"(al.x), "f"(al.y), "f"(al.z), "f"(al.w) : "memory");
    asm("st.global.cs.v4.f32 [%0], {%1, %2, %3, %4};"
        :: "l"(ob + s_hi), "f"(ah.x), "f"(ah.y), "f"(ah.z), "f"(ah.w) : "memory");
}

extern "C" void kernel_launch(void* const* d_in, const int* in_sizes, int n_in,
                              void* d_out, int out_size)
{
    const float* x   = (const float*)d_in[0];   // [16, 64, 32768] float32
    const int*   idx = (const int*)  d_in[1];   // [16, 64] int32
    float*       out = (float*)d_out;           // [16, 1, 32768] float32

    dim3 block(64);
    dim3 grid(NTILES / 2, BATCH);               // (64, 16) = 1024 blocks
    sparse_audio_gather<<<grid, block>>>(x, idx, out);
}